// round 8
// baseline (speedup 1.0000x reference)
#include <cuda_runtime.h>
#include <cuda_bf16.h>
#include <cstdint>

#define T_STEPS 1024
#define BATCH   128
#define FEAT    88
#define HID     1024
#define CLS     88
#define KTOT    1112          // HID + FEAT
#define KP      1152          // padded K
#define WS_STRIDE 1168        // resident-W row stride (halfs): 8-bank shift/row
#define NCTA    128
#define NTHR    512
#define MT      64            // batch rows per CTA
#define UPC     16            // hidden units per CTA -> 64 gate cols
#define CW      128           // A chunk width (K cols)
#define NSEQ    9             // chunks per step (1 x + 8 h)
#define ASTR    136           // A-tile row stride (halfs)
#define NBUF    4             // A-stage ring buffers
#define GSM_STRIDE 68
#define FC_ASTR 72

// ---------------- device globals ----------------
__device__ __nv_bfloat16 g_Wc[(size_t)4096 * KP];                  // combined [W_hh | W_ih | pad], bf16
__device__ __nv_bfloat16 g_Wfcb[(size_t)CLS * HID];                // W_fc bf16
__device__ float         g_bsum[4096];                             // b_ih + b_hh
__device__ __nv_bfloat16 g_xb[(size_t)T_STEPS * BATCH * FEAT];     // x in bf16
__device__ __nv_bfloat16 g_h[2][BATCH * HID];                      // double-buffered hidden state
__device__ __nv_bfloat16 g_Hall[(size_t)T_STEPS * BATCH * HID];    // all h_t for FC
__device__ int           g_flag[NCTA * 4];                         // per-CTA step flags (16B padded)

// ---------------- helpers ----------------
__device__ __forceinline__ unsigned smem_u32(const void* p) {
    return (unsigned)__cvta_generic_to_shared(p);
}
__device__ __forceinline__ float sigmoidf_(float x) {
    return 1.0f / (1.0f + __expf(-x));
}
__device__ __forceinline__ float tanhf_(float x) {
    float ax = fabsf(x);
    float e  = __expf(-2.0f * ax);
    float r  = (1.0f - e) / (1.0f + e);
    return (x < 0.0f) ? -r : r;
}

#define MMA_BF16(ACC, A0, A1, A2, A3, B0, B1)                                             \
    asm volatile(                                                                         \
        "mma.sync.aligned.m16n8k16.row.col.f32.bf16.bf16.f32 "                            \
        "{%0,%1,%2,%3}, {%4,%5,%6,%7}, {%8,%9}, {%0,%1,%2,%3};\n"                         \
        : "+f"((ACC)[0]), "+f"((ACC)[1]), "+f"((ACC)[2]), "+f"((ACC)[3])                  \
        : "r"(A0), "r"(A1), "r"(A2), "r"(A3), "r"(B0), "r"(B1))

#define LDMATRIX_X4(R0, R1, R2, R3, ADDR)                                                 \
    asm volatile("ldmatrix.sync.aligned.m8n8.x4.shared.b16 {%0,%1,%2,%3}, [%4];\n"        \
                 : "=r"(R0), "=r"(R1), "=r"(R2), "=r"(R3) : "r"(ADDR))

#define LDS64(R0, R1, ADDR)                                                               \
    asm volatile("ld.shared.v2.u32 {%0,%1}, [%2];" : "=r"(R0), "=r"(R1) : "r"(ADDR))

#define CP_ASYNC16(DST, SRC)                                                              \
    asm volatile("cp.async.cg.shared.global [%0], [%1], 16;\n" :: "r"(DST), "l"(SRC))
#define CP_ASYNC16_ZFILL(DST, SRC)                                                        \
    asm volatile("cp.async.cg.shared.global [%0], [%1], 16, %2;\n"                        \
                 :: "r"(DST), "l"(SRC), "r"(0))
#define CP_COMMIT  asm volatile("cp.async.commit_group;\n")
#define CP_WAIT(N) asm volatile("cp.async.wait_group %0;\n" :: "n"(N))

// ---------------- prep kernels (lstm_kernel must stay the 4th launch for ncu) ----------------
__global__ void init_kernel() {
    int idx = blockIdx.x * blockDim.x + threadIdx.x;
    uint4 z = make_uint4(0u, 0u, 0u, 0u);
    for (int i = idx; i < 32768; i += gridDim.x * blockDim.x)
        reinterpret_cast<uint4*>(g_h)[i] = z;
    if (idx < NCTA * 4) g_flag[idx] = 0;
}

__global__ void prep_all_kernel(const float* __restrict__ Wih, const float* __restrict__ Whh,
                                const float* __restrict__ bih, const float* __restrict__ bhh,
                                const float* __restrict__ Wfc) {
    size_t idx = (size_t)blockIdx.x * blockDim.x + threadIdx.x;
    size_t total = (size_t)4096 * KP;
    if (idx < total) {
        int n = (int)(idx / KP);
        int k = (int)(idx % KP);
        float v = 0.0f;
        if (k < HID)        v = Whh[(size_t)n * HID + k];
        else if (k < KTOT)  v = Wih[(size_t)n * FEAT + (k - HID)];
        g_Wc[idx] = __float2bfloat16(v);
    }
    if (idx < 4096) g_bsum[idx] = bih[idx] + bhh[idx];
    if (idx < (size_t)CLS * HID) g_Wfcb[idx] = __float2bfloat16(Wfc[idx]);
}

__global__ void prep_x_kernel(const float* __restrict__ x) {
    size_t idx = (size_t)blockIdx.x * blockDim.x + threadIdx.x;
    size_t total = (size_t)T_STEPS * BATCH * FEAT;
    if (idx < total) g_xb[idx] = __float2bfloat16(x[idx]);
}

// ---------------- persistent LSTM step kernel ----------------
// 128 CTAs, 512 threads (16 warps, 4x4 warp grid: 16x16 out tile per warp).
// CTA (m,n): m = bid&1 (64 batch rows), n = bid>>1 (16 units -> 64 gate cols).
// Half-barrier on 64 same-half flags with release/acquire publish.
// 9 K-chunks of 128 via cp.async 4-buffer ring (depth 3). gsm aliases buf 1.
// g_Hall store happens AFTER flag publish (no inter-CTA consumer).
__global__ void __launch_bounds__(NTHR, 1)
lstm_kernel(const int* __restrict__ lens)
{
    extern __shared__ char smem_raw[];
    __nv_bfloat16* Ws  = reinterpret_cast<__nv_bfloat16*>(smem_raw);        // 64 * WS_STRIDE
    __nv_bfloat16* As  = Ws + 64 * WS_STRIDE;                               // NBUF * 64 * ASTR
    float* gsm         = reinterpret_cast<float*>(As + 64 * ASTR);          // aliases ring buf 1
    float* bias_s      = reinterpret_cast<float*>(As + NBUF * 64 * ASTR);   // 64
    int*   len_s       = reinterpret_cast<int*>(bias_s + 64);               // 64

    const int tid   = threadIdx.x;
    const int bid   = blockIdx.x;
    const int cta_m = bid & 1;
    const int cta_n = bid >> 1;
    const int b0    = cta_m * MT;
    const int hid0  = cta_n * UPC;

    // Resident W slice, k-permuted per 16-half group (pair q <- pair (q>>1)+((q&1)<<2))
    for (int i = tid; i < 64 * (KP / 2); i += NTHR) {
        int n = i / (KP / 2), j = i % (KP / 2);
        int g16 = j >> 3, q = j & 7;
        int sp  = (q >> 1) + ((q & 1) << 2);
        int g = n >> 4, u = n & 15;
        const unsigned* src = reinterpret_cast<const unsigned*>(
                g_Wc + (size_t)(g * HID + hid0 + u) * KP);
        reinterpret_cast<unsigned*>(Ws + (size_t)n * WS_STRIDE)[j] = src[g16 * 8 + sp];
    }
    if (tid < 64) {
        int g = tid >> 4, u = tid & 15;
        bias_s[tid] = g_bsum[g * HID + hid0 + u];
    } else if (tid < 128) {
        len_s[tid - 64] = lens[b0 + (tid - 64)];
    }
    __syncthreads();

    const int lane = tid & 31, wid = tid >> 5;
    const int wm = wid & 3;        // 0..3 : 16 rows each
    const int wn = wid >> 2;       // 0..3 : 16 cols each
    const int eu  = tid & 15;      // epilogue: unit
    const int eb  = tid >> 4;      // epilogue: batch row (0..31; rows eb, eb+32)

    const unsigned ws_u = smem_u32(Ws);
    const unsigned as_u = smem_u32(As);

    // barrier watchers: tid<64 watch same-half producer flags
    const bool watcher = (tid < 64);
    int* const my_fp   = &g_flag[(((tid & 63) << 1) | cta_m) << 2];

    float hreg[2] = {0.f, 0.f};
    float creg[2] = {0.f, 0.f};

    for (int t = 0; t < T_STEPS; ++t) {
        const __nv_bfloat16* __restrict__ h_cur = g_h[t & 1];
        __nv_bfloat16* __restrict__ h_nxt = g_h[(t & 1) ^ 1];

        // stage chunk s into ring buf s&3. s==0 -> x (cols 1024..), else h.
        auto stage = [&](int s) {
            unsigned dstb = as_u + (unsigned)((s & 3) * 64 * ASTR * 2);
#pragma unroll
            for (int r = 0; r < 2; ++r) {
                int slot = tid + r * NTHR;           // 1024 slots = 64 rows x 16 seg
                int row = slot >> 4, c16 = slot & 15;
                unsigned dst = dstb + (unsigned)((row * ASTR + c16 * 8) * 2);
                if (s >= 1) {
                    CP_ASYNC16(dst, h_cur + (size_t)(b0 + row) * HID + (s - 1) * CW + c16 * 8);
                } else {
                    int f = c16 * 8;
                    if (f + 8 <= FEAT) {
                        CP_ASYNC16(dst, g_xb + ((size_t)t * BATCH + b0 + row) * FEAT + f);
                    } else {
                        CP_ASYNC16_ZFILL(dst, g_xb);
                    }
                }
            }
            CP_COMMIT;
        };

        // x chunk is h-independent: stage before the barrier
        stage(0);

        // half-barrier (acquire): the 64 same-half CTAs published step t-1
        if (t > 0) {
            int fv = 0x7fffffff;
            if (watcher)
                asm volatile("ld.acquire.gpu.global.b32 %0, [%1];" : "=r"(fv) : "l"(my_fp) : "memory");
            for (;;) {
                if (__syncthreads_count(fv >= t) == NTHR) break;
                if (watcher && fv < t)
                    asm volatile("ld.acquire.gpu.global.b32 %0, [%1];" : "=r"(fv) : "l"(my_fp) : "memory");
            }
        }

        stage(1);
        stage(2);

        float acc[2][4];
#pragma unroll
        for (int b = 0; b < 2; ++b)
#pragma unroll
            for (int c = 0; c < 4; ++c) acc[b][c] = 0.f;

        for (int s = 0; s < NSEQ; ++s) {
            if (s < NSEQ - 2)      { CP_WAIT(2); }
            else if (s == NSEQ - 2){ CP_WAIT(1); }
            else                   { CP_WAIT(0); }
            __syncthreads();
            if (s + 3 < NSEQ) stage(s + 3);

            const int kcol  = (s == 0) ? HID : ((s - 1) * CW);
            const int ksmax = (s == 0) ? 6 : 8;     // x-chunk cols 1120..1151 are pad
            const unsigned abase = as_u + (unsigned)((s & 3) * 64 * ASTR * 2);
            for (int ks = 0; ks < ksmax; ++ks) {
                const int kk = ks * 16;
                const int kg = kcol + kk;
                unsigned a0, a1, a2, a3;
                unsigned addr = abase +
                    (unsigned)(((wm * 16 + (lane & 15)) * ASTR + kk + ((lane >> 4) << 3)) * 2);
                LDMATRIX_X4(a0, a1, a2, a3, addr);
#pragma unroll
                for (int nf = 0; nf < 2; ++nf) {
                    int n = wn * 16 + nf * 8 + (lane >> 2);
                    unsigned baddr = ws_u +
                        (unsigned)((n * WS_STRIDE + kg) * 2) + ((lane & 3) << 3);
                    unsigned b0r, b1r;
                    LDS64(b0r, b1r, baddr);
                    MMA_BF16(acc[nf], a0, a1, a2, a3, b0r, b1r);
                }
            }
        }
        __syncthreads();

        // accumulators -> gsm (aliases ring buf 1; all computes done)
        {
            int r = wm * 16 + (lane >> 2);
#pragma unroll
            for (int nf = 0; nf < 2; ++nf) {
                int c = wn * 16 + nf * 8 + ((lane & 3) << 1);
                gsm[r * GSM_STRIDE + c]           = acc[nf][0];
                gsm[r * GSM_STRIDE + c + 1]       = acc[nf][1];
                gsm[(r + 8) * GSM_STRIDE + c]     = acc[nf][2];
                gsm[(r + 8) * GSM_STRIDE + c + 1] = acc[nf][3];
            }
        }
        __syncthreads();

        // LSTM cell: thread owns rows (eb, eb+32), unit eu
#pragma unroll
        for (int p = 0; p < 2; ++p) {
            int bl = eb + p * 32;
            float gi = gsm[bl * GSM_STRIDE + eu]        + bias_s[eu];
            float gf = gsm[bl * GSM_STRIDE + 16 + eu]   + bias_s[16 + eu];
            float gg = gsm[bl * GSM_STRIDE + 32 + eu]   + bias_s[32 + eu];
            float go = gsm[bl * GSM_STRIDE + 48 + eu]   + bias_s[48 + eu];
            float ii = sigmoidf_(gi);
            float ff = sigmoidf_(gf);
            float gt = tanhf_(gg);
            float oo = sigmoidf_(go);
            float cn = ff * creg[p] + ii * gt;
            float hn = oo * tanhf_(cn);
            bool  m  = t < len_s[bl];
            float h2 = m ? hn : hreg[p];
            creg[p]  = m ? cn : creg[p];
            hreg[p]  = h2;
            h_nxt[(b0 + bl) * HID + hid0 + eu] = __float2bfloat16(h2);
        }

        // publish step t (barrier + single release store = grid-sync pattern)
        __syncthreads();
        if (tid == 0)
            asm volatile("st.release.gpu.global.b32 [%0], %1;"
                         :: "l"(&g_flag[bid << 2]), "r"(t + 1) : "memory");

        // g_Hall has no inter-CTA consumer: store after publish (off critical path)
#pragma unroll
        for (int p = 0; p < 2; ++p) {
            int bl = eb + p * 32;
            g_Hall[((size_t)t * BATCH + b0 + bl) * HID + hid0 + eu] =
                __float2bfloat16(hreg[p]);
        }
    }
}

// ---------------- FC head: logits + binary expansion ----------------
__global__ void __launch_bounds__(128)
fc_kernel(const int* __restrict__ lens, const float* __restrict__ bfc,
          float* __restrict__ out)
{
    __shared__ __nv_bfloat16 As[64 * FC_ASTR];
    __shared__ __nv_bfloat16 Bs[88 * FC_ASTR];

    const int tid  = threadIdx.x;
    const int lane = tid & 31, wid = tid >> 5;
    const int r0   = blockIdx.x * 64;   // rows of H_all (tb = t*128 + b)

    float acc[11][4];
#pragma unroll
    for (int i = 0; i < 11; ++i)
#pragma unroll
        for (int j = 0; j < 4; ++j) acc[i][j] = 0.f;

    const unsigned as_u = smem_u32(As);
    const unsigned bs_u = smem_u32(Bs);

    for (int ch = 0; ch < 16; ++ch) {
        __syncthreads();
        const int k0 = ch * 64;
        for (int i = tid; i < 512; i += 128) {          // A: 64 rows x 8 uint4
            int row = i >> 3, c8 = i & 7;
            uint4 v = *(reinterpret_cast<const uint4*>(
                    g_Hall + (size_t)(r0 + row) * HID + k0) + c8);
            *(reinterpret_cast<uint4*>(As + row * FC_ASTR) + c8) = v;
        }
        for (int i = tid; i < 704; i += 128) {          // B: 88 rows x 8 uint4
            int row = i >> 3, c8 = i & 7;
            uint4 v = *(reinterpret_cast<const uint4*>(
                    g_Wfcb + (size_t)row * HID + k0) + c8);
            *(reinterpret_cast<uint4*>(Bs + row * FC_ASTR) + c8) = v;
        }
        __syncthreads();
#pragma unroll
        for (int ks = 0; ks < 4; ++ks) {
            int kk = ks * 16;
            unsigned a0, a1, a2, a3;
            unsigned addr = as_u +
                (unsigned)(((wid * 16 + (lane & 15)) * FC_ASTR + kk + ((lane >> 4) << 3)) * 2);
            LDMATRIX_X4(a0, a1, a2, a3, addr);
#pragma unroll
            for (int nf = 0; nf < 11; ++nf) {
                int n = nf * 8 + (lane >> 2);
                unsigned baddr = bs_u +
                    (unsigned)((n * FC_ASTR + kk + ((lane & 3) << 1)) * 2);
                unsigned b0r, b1r;
                asm volatile("ld.shared.b32 %0, [%1];" : "=r"(b0r) : "r"(baddr));
                asm volatile("ld.shared.b32 %0, [%1];" : "=r"(b1r) : "r"(baddr + 16));
                MMA_BF16(acc[nf], a0, a1, a2, a3, b0r, b1r);
            }
        }
    }

#pragma unroll
    for (int half = 0; half < 2; ++half) {
        int r  = wid * 16 + (lane >> 2) + half * 8;
        int tb = r0 + r;
        int t  = tb >> 7;
        int b  = tb & 127;
        bool m = t < __ldg(lens + b);
        size_t obase = ((size_t)b * T_STEPS + t) * CLS * 2;
#pragma unroll
        for (int nf = 0; nf < 11; ++nf) {
            int c = nf * 8 + ((lane & 3) << 1);
            float l0 = acc[nf][half * 2 + 0] + __ldg(bfc + c);
            float l1 = acc[nf][half * 2 + 1] + __ldg(bfc + c + 1);
            if (!m) { l0 = 0.f; l1 = 0.f; }
            float4 v = make_float4(l0, 1.f - l0, l1, 1.f - l1);
            *reinterpret_cast<float4*>(out + obase + (size_t)c * 2) = v;
        }
    }
}

// ---------------- launch ----------------
extern "C" void kernel_launch(void* const* d_in, const int* in_sizes, int n_in,
                              void* d_out, int out_size) {
    const float* x    = (const float*)d_in[0];
    const int*   lens = (const int*)d_in[1];    // int32 (JAX x64 disabled)
    const float* Wih  = (const float*)d_in[2];
    const float* Whh  = (const float*)d_in[3];
    const float* bih  = (const float*)d_in[4];
    const float* bhh  = (const float*)d_in[5];
    const float* Wfc  = (const float*)d_in[6];
    const float* bfc  = (const float*)d_in[7];
    float*       out  = (float*)d_out;
    (void)in_sizes; (void)n_in; (void)out_size;

    // lstm_kernel is the 4th launch (ncu capture slot)
    init_kernel<<<64, 256>>>();
    {
        size_t tot = (size_t)4096 * KP;
        prep_all_kernel<<<(unsigned)((tot + 255) / 256), 256>>>(Wih, Whh, bih, bhh, Wfc);
    }
    {
        size_t tot = (size_t)T_STEPS * BATCH * FEAT;
        prep_x_kernel<<<(unsigned)((tot + 255) / 256), 256>>>(x);
    }

    int smem = 64 * WS_STRIDE * 2          // resident W slice   (149504)
             + NBUF * 64 * ASTR * 2        // A-stage ring       (69632)
             + 64 * 4 + 64 * 4;            // bias + lengths
    cudaFuncSetAttribute(lstm_kernel, cudaFuncAttributeMaxDynamicSharedMemorySize, smem);
    lstm_kernel<<<NCTA, NTHR, smem>>>(lens);

    fc_kernel<<<(T_STEPS * BATCH) / 64, 128>>>(lens, bfc, out);
}

// round 9
// speedup vs baseline: 1.0411x; 1.0411x over previous
#include <cuda_runtime.h>
#include <cuda_bf16.h>
#include <cstdint>

#define T_STEPS 1024
#define BATCH   128
#define FEAT    88
#define HID     1024
#define CLS     88
#define KTOT    1112          // HID + FEAT
#define KP      1152          // padded K
#define WS_STRIDE 1168        // resident-W row stride (halfs)
#define NCTA    128
#define NTHR    384           // 8 consumer warps + 4 producer warps
#define NCONS   256
#define NPROD   128
#define MT      64            // batch rows per CTA
#define UPC     16            // hidden units per CTA -> 64 gate cols
#define CW      128           // A chunk width (K cols)
#define ASTR    136           // A-tile row stride (halfs)
#define GSM_STRIDE 68
#define FC_ASTR 72

// named barrier ids: EMPTY[b]=1+b, FULL[b]=5+b, CONS=9, PROD=10
#define BAR_SYNC(ID, CNT)   asm volatile("bar.sync %0, %1;"   :: "r"(ID), "r"(CNT) : "memory")
#define BAR_ARRIVE(ID, CNT) asm volatile("bar.arrive %0, %1;" :: "r"(ID), "r"(CNT) : "memory")

// ---------------- device globals ----------------
__device__ __nv_bfloat16 g_Wc[(size_t)4096 * KP];
__device__ __nv_bfloat16 g_Wfcb[(size_t)CLS * HID];
__device__ float         g_bsum[4096];
__device__ __nv_bfloat16 g_xb[(size_t)T_STEPS * BATCH * FEAT];
__device__ __nv_bfloat16 g_h[2][BATCH * HID];
__device__ __nv_bfloat16 g_Hall[(size_t)T_STEPS * BATCH * HID];
__device__ int           g_flag[NCTA * 4];

// ---------------- helpers ----------------
__device__ __forceinline__ unsigned smem_u32(const void* p) {
    return (unsigned)__cvta_generic_to_shared(p);
}
__device__ __forceinline__ float sigmoidf_(float x) {
    return 1.0f / (1.0f + __expf(-x));
}
__device__ __forceinline__ float tanhf_(float x) {
    float ax = fabsf(x);
    float e  = __expf(-2.0f * ax);
    float r  = (1.0f - e) / (1.0f + e);
    return (x < 0.0f) ? -r : r;
}

#define MMA_BF16(ACC, A0, A1, A2, A3, B0, B1)                                             \
    asm volatile(                                                                         \
        "mma.sync.aligned.m16n8k16.row.col.f32.bf16.bf16.f32 "                            \
        "{%0,%1,%2,%3}, {%4,%5,%6,%7}, {%8,%9}, {%0,%1,%2,%3};\n"                         \
        : "+f"((ACC)[0]), "+f"((ACC)[1]), "+f"((ACC)[2]), "+f"((ACC)[3])                  \
        : "r"(A0), "r"(A1), "r"(A2), "r"(A3), "r"(B0), "r"(B1))

#define LDMATRIX_X4(R0, R1, R2, R3, ADDR)                                                 \
    asm volatile("ldmatrix.sync.aligned.m8n8.x4.shared.b16 {%0,%1,%2,%3}, [%4];\n"        \
                 : "=r"(R0), "=r"(R1), "=r"(R2), "=r"(R3) : "r"(ADDR))

#define LDS64(R0, R1, ADDR)                                                               \
    asm volatile("ld.shared.v2.u32 {%0,%1}, [%2];" : "=r"(R0), "=r"(R1) : "r"(ADDR))

#define CP_ASYNC16(DST, SRC)                                                              \
    asm volatile("cp.async.cg.shared.global [%0], [%1], 16;\n" :: "r"(DST), "l"(SRC))
#define CP_ASYNC16_ZFILL(DST, SRC)                                                        \
    asm volatile("cp.async.cg.shared.global [%0], [%1], 16, %2;\n"                        \
                 :: "r"(DST), "l"(SRC), "r"(0))
#define CP_COMMIT  asm volatile("cp.async.commit_group;\n")
#define CP_WAIT(N) asm volatile("cp.async.wait_group %0;\n" :: "n"(N))

// ---------------- prep kernels (lstm_kernel stays the 4th launch) ----------------
__global__ void init_kernel() {
    int idx = blockIdx.x * blockDim.x + threadIdx.x;
    uint4 z = make_uint4(0u, 0u, 0u, 0u);
    for (int i = idx; i < 32768; i += gridDim.x * blockDim.x)
        reinterpret_cast<uint4*>(g_h)[i] = z;
    if (idx < NCTA * 4) g_flag[idx] = 0;
}

__global__ void prep_all_kernel(const float* __restrict__ Wih, const float* __restrict__ Whh,
                                const float* __restrict__ bih, const float* __restrict__ bhh,
                                const float* __restrict__ Wfc) {
    size_t idx = (size_t)blockIdx.x * blockDim.x + threadIdx.x;
    size_t total = (size_t)4096 * KP;
    if (idx < total) {
        int n = (int)(idx / KP);
        int k = (int)(idx % KP);
        float v = 0.0f;
        if (k < HID)        v = Whh[(size_t)n * HID + k];
        else if (k < KTOT)  v = Wih[(size_t)n * FEAT + (k - HID)];
        g_Wc[idx] = __float2bfloat16(v);
    }
    if (idx < 4096) g_bsum[idx] = bih[idx] + bhh[idx];
    if (idx < (size_t)CLS * HID) g_Wfcb[idx] = __float2bfloat16(Wfc[idx]);
}

__global__ void prep_x_kernel(const float* __restrict__ x) {
    size_t idx = (size_t)blockIdx.x * blockDim.x + threadIdx.x;
    size_t total = (size_t)T_STEPS * BATCH * FEAT;
    if (idx < total) g_xb[idx] = __float2bfloat16(x[idx]);
}

// ---------------- persistent LSTM kernel: producer/consumer warp specialization ----------------
// 128 CTAs, 384 threads. Warps 0-7: MMA consumers (R7 layout). Warps 8-11:
// producers (all cp.async staging + inter-CTA flag spin). Chunks per step:
// c0 = x (prefetched during PREVIOUS step tail), c1..c8 = h (K=128 each).
// Buffers: B0-B2 rotate (c s -> s%3), c8 -> B3; gsm (gate exchange) aliases B3.
// Per-buffer named-barrier FULL/EMPTY handshakes; consumers never CP_WAIT.
__global__ void __launch_bounds__(NTHR, 1)
lstm_kernel(const int* __restrict__ lens)
{
    extern __shared__ char smem_raw[];
    __nv_bfloat16* Ws  = reinterpret_cast<__nv_bfloat16*>(smem_raw);        // 64 * WS_STRIDE
    __nv_bfloat16* As  = Ws + 64 * WS_STRIDE;                               // 4 * 64 * ASTR
    float* gsm         = reinterpret_cast<float*>(As + 3 * 64 * ASTR);      // aliases B3
    float* bias_s      = reinterpret_cast<float*>(As + 4 * 64 * ASTR);      // 64
    int*   len_s       = reinterpret_cast<int*>(bias_s + 64);               // 64

    const int tid   = threadIdx.x;
    const int bid   = blockIdx.x;
    const int cta_m = bid & 1;
    const int cta_n = bid >> 1;
    const int b0    = cta_m * MT;
    const int hid0  = cta_n * UPC;

    // resident W slice, k-permuted per 16-half group (pair q <- pair (q>>1)+((q&1)<<2))
    for (int i = tid; i < 64 * (KP / 2); i += NTHR) {
        int n = i / (KP / 2), j = i % (KP / 2);
        int g16 = j >> 3, q = j & 7;
        int sp  = (q >> 1) + ((q & 1) << 2);
        int g = n >> 4, u = n & 15;
        const unsigned* src = reinterpret_cast<const unsigned*>(
                g_Wc + (size_t)(g * HID + hid0 + u) * KP);
        reinterpret_cast<unsigned*>(Ws + (size_t)n * WS_STRIDE)[j] = src[g16 * 8 + sp];
    }
    if (tid < 64) {
        int g = tid >> 4, u = tid & 15;
        bias_s[tid] = g_bsum[g * HID + hid0 + u];
    } else if (tid < 128) {
        len_s[tid - 64] = lens[b0 + (tid - 64)];
    }
    __syncthreads();

    const unsigned ws_u = smem_u32(Ws);
    const unsigned as_u = smem_u32(As);
    const int wid = tid >> 5;

    if (wid < 8) {
        // ================= CONSUMERS (warps 0-7) =================
        const int lane = tid & 31;
        const int wm = wid & 1;        // 0..1 : 32 rows
        const int wn = wid >> 1;       // 0..3 : 16 cols
        const int eu  = tid & 15;
        const int eb0 = tid >> 4;      // 0..15

        float hreg[4] = {0.f, 0.f, 0.f, 0.f};
        float creg[4] = {0.f, 0.f, 0.f, 0.f};

        for (int t = 0; t < T_STEPS; ++t) {
            __nv_bfloat16* __restrict__ h_nxt = g_h[(t & 1) ^ 1];

            float acc[2][2][4];
#pragma unroll
            for (int a = 0; a < 2; ++a)
#pragma unroll
                for (int b = 0; b < 2; ++b)
#pragma unroll
                    for (int c = 0; c < 4; ++c) acc[a][b][c] = 0.f;

#pragma unroll
            for (int s = 0; s < 9; ++s) {
                const int bf    = (s == 8) ? 3 : (s % 3);
                const int kcol  = (s == 0) ? HID : ((s - 1) * CW);
                const int ksmax = (s == 0) ? 6 : 8;
                BAR_SYNC(5 + bf, NTHR);
                const unsigned abase = as_u + (unsigned)(bf * 64 * ASTR * 2);
#pragma unroll
                for (int ks = 0; ks < ksmax; ++ks) {
                    const int kk = ks * 16;
                    const int kg = kcol + kk;
                    unsigned a[2][4];
#pragma unroll
                    for (int mi = 0; mi < 2; ++mi) {
                        unsigned addr = abase +
                            (unsigned)(((wm * 32 + mi * 16 + (lane & 15)) * ASTR +
                                        kk + ((lane >> 4) << 3)) * 2);
                        LDMATRIX_X4(a[mi][0], a[mi][1], a[mi][2], a[mi][3], addr);
                    }
#pragma unroll
                    for (int nf = 0; nf < 2; ++nf) {
                        int n = wn * 16 + nf * 8 + (lane >> 2);
                        unsigned baddr = ws_u +
                            (unsigned)((n * WS_STRIDE + kg) * 2) + ((lane & 3) << 3);
                        unsigned b0r, b1r;
                        LDS64(b0r, b1r, baddr);
#pragma unroll
                        for (int mi = 0; mi < 2; ++mi) {
                            MMA_BF16(acc[mi][nf], a[mi][0], a[mi][1], a[mi][2], a[mi][3], b0r, b1r);
                        }
                    }
                }
                if (s < 8) BAR_ARRIVE(1 + bf, NTHR);
            }

            // all consumers done reading B3 (c8) before gsm overwrites it
            BAR_SYNC(9, NCONS);
#pragma unroll
            for (int mi = 0; mi < 2; ++mi) {
                int r = wm * 32 + mi * 16 + (lane >> 2);
#pragma unroll
                for (int nf = 0; nf < 2; ++nf) {
                    int c = wn * 16 + nf * 8 + ((lane & 3) << 1);
                    gsm[r * GSM_STRIDE + c]           = acc[mi][nf][0];
                    gsm[r * GSM_STRIDE + c + 1]       = acc[mi][nf][1];
                    gsm[(r + 8) * GSM_STRIDE + c]     = acc[mi][nf][2];
                    gsm[(r + 8) * GSM_STRIDE + c + 1] = acc[mi][nf][3];
                }
            }
            BAR_SYNC(9, NCONS);

            // LSTM cell: thread owns (b_local = eb0 + 16p, unit = eu)
#pragma unroll
            for (int p = 0; p < 4; ++p) {
                int bl = eb0 + p * 16;
                float gi = gsm[bl * GSM_STRIDE + eu]        + bias_s[eu];
                float gf = gsm[bl * GSM_STRIDE + 16 + eu]   + bias_s[16 + eu];
                float gg = gsm[bl * GSM_STRIDE + 32 + eu]   + bias_s[32 + eu];
                float go = gsm[bl * GSM_STRIDE + 48 + eu]   + bias_s[48 + eu];
                float ii = sigmoidf_(gi);
                float ff = sigmoidf_(gf);
                float gt = tanhf_(gg);
                float oo = sigmoidf_(go);
                float cn = ff * creg[p] + ii * gt;
                float hn = oo * tanhf_(cn);
                bool  m  = t < len_s[bl];
                float h2 = m ? hn : hreg[p];
                creg[p]  = m ? cn : creg[p];
                hreg[p]  = h2;
                h_nxt[(b0 + bl) * HID + hid0 + eu] = __float2bfloat16(h2);
            }

            // publish: fence all consumer stores, sync, single flag store
            __threadfence();
            BAR_SYNC(9, NCONS);
            if (tid == 0) __stcg(&g_flag[bid << 2], t + 1);
            BAR_ARRIVE(4, NTHR);          // EMPTY[B3]: gsm reads complete

            // g_Hall: no inter-CTA consumer -> off critical path
#pragma unroll
            for (int p = 0; p < 4; ++p) {
                int bl = eb0 + p * 16;
                g_Hall[((size_t)t * BATCH + b0 + bl) * HID + hid0 + eu] =
                    __float2bfloat16(hreg[p]);
            }
        }
    } else {
        // ================= PRODUCERS (warps 8-11) =================
        const int ptid = tid - NCONS;     // 0..127
        int* const my_fp = &g_flag[(((ptid & 63) << 1) | cta_m) << 2];
        const bool watcher = (ptid < 64);

        auto stage_h = [&](int t, int s, int bf) {
            const __nv_bfloat16* __restrict__ h_cur = g_h[t & 1];
            unsigned dstb = as_u + (unsigned)(bf * 64 * ASTR * 2);
#pragma unroll
            for (int r = 0; r < 8; ++r) {
                int slot = ptid + r * NPROD;       // 1024 slots = 64 rows x 16 seg
                int row = slot >> 4, c16 = slot & 15;
                unsigned dst = dstb + (unsigned)((row * ASTR + c16 * 8) * 2);
                CP_ASYNC16(dst, h_cur + (size_t)(b0 + row) * HID + (s - 1) * CW + c16 * 8);
            }
            CP_COMMIT;
        };
        auto stage_x = [&](int tx) {
#pragma unroll
            for (int r = 0; r < 8; ++r) {
                int slot = ptid + r * NPROD;
                int row = slot >> 4, c16 = slot & 15;
                unsigned dst = as_u + (unsigned)((row * ASTR + c16 * 8) * 2);   // B0
                int f = c16 * 8;
                if (f + 8 <= FEAT) {
                    CP_ASYNC16(dst, g_xb + ((size_t)tx * BATCH + b0 + row) * FEAT + f);
                } else {
                    CP_ASYNC16_ZFILL(dst, g_xb);
                }
            }
            CP_COMMIT;
        };

        stage_x(0);                        // c0 of t=0 (the "gX" invariant group)

        for (int t = 0; t < T_STEPS; ++t) {
            // inter-CTA half-barrier: 64 same-half flags >= t
            if (t > 0) {
                if (watcher) {
                    int fv;
                    do {
                        asm volatile("ld.acquire.gpu.global.b32 %0, [%1];"
                                     : "=r"(fv) : "l"(my_fp) : "memory");
                    } while (fv < t);
                }
                BAR_SYNC(10, NPROD);
            }

            if (t > 0) BAR_SYNC(2, NTHR);  // EMPTY[B1]
            stage_h(t, 1, 1);
            if (t > 0) BAR_SYNC(3, NTHR);  // EMPTY[B2]
            stage_h(t, 2, 2);
            CP_WAIT(2); BAR_ARRIVE(5 + 0, NTHR);     // c0 (x, prefetched) ready

            BAR_SYNC(1, NTHR); stage_h(t, 3, 0);     // EMPTY[B0] (c0 consumed)
            CP_WAIT(2); BAR_ARRIVE(5 + 1, NTHR);     // c1 ready
            BAR_SYNC(2, NTHR); stage_h(t, 4, 1);
            CP_WAIT(2); BAR_ARRIVE(5 + 2, NTHR);     // c2 ready
            BAR_SYNC(3, NTHR); stage_h(t, 5, 2);
            CP_WAIT(2); BAR_ARRIVE(5 + 0, NTHR);     // c3 ready
            BAR_SYNC(1, NTHR); stage_h(t, 6, 0);
            CP_WAIT(2); BAR_ARRIVE(5 + 1, NTHR);     // c4 ready
            BAR_SYNC(2, NTHR); stage_h(t, 7, 1);
            CP_WAIT(2); BAR_ARRIVE(5 + 2, NTHR);     // c5 ready
            if (t > 0) BAR_SYNC(4, NTHR);  // EMPTY[B3] (prev epilogue done)
            stage_h(t, 8, 3);
            CP_WAIT(2); BAR_ARRIVE(5 + 0, NTHR);     // c6 ready
            BAR_SYNC(1, NTHR);             // EMPTY[B0] (c6 consumed)
            stage_x(t + 1 < T_STEPS ? t + 1 : T_STEPS - 1);   // prefetch next x
            CP_WAIT(2); BAR_ARRIVE(5 + 1, NTHR);     // c7 ready
            CP_WAIT(1); BAR_ARRIVE(5 + 3, NTHR);     // c8 ready (next-x stays in flight)
        }
    }
}

// ---------------- FC head: logits + binary expansion ----------------
__global__ void __launch_bounds__(128)
fc_kernel(const int* __restrict__ lens, const float* __restrict__ bfc,
          float* __restrict__ out)
{
    __shared__ __nv_bfloat16 As[64 * FC_ASTR];
    __shared__ __nv_bfloat16 Bs[88 * FC_ASTR];

    const int tid  = threadIdx.x;
    const int lane = tid & 31, wid = tid >> 5;
    const int r0   = blockIdx.x * 64;   // rows of H_all (tb = t*128 + b)

    float acc[11][4];
#pragma unroll
    for (int i = 0; i < 11; ++i)
#pragma unroll
        for (int j = 0; j < 4; ++j) acc[i][j] = 0.f;

    const unsigned as_u = smem_u32(As);
    const unsigned bs_u = smem_u32(Bs);

    for (int ch = 0; ch < 16; ++ch) {
        __syncthreads();
        const int k0 = ch * 64;
        for (int i = tid; i < 512; i += 128) {
            int row = i >> 3, c8 = i & 7;
            uint4 v = *(reinterpret_cast<const uint4*>(
                    g_Hall + (size_t)(r0 + row) * HID + k0) + c8);
            *(reinterpret_cast<uint4*>(As + row * FC_ASTR) + c8) = v;
        }
        for (int i = tid; i < 704; i += 128) {
            int row = i >> 3, c8 = i & 7;
            uint4 v = *(reinterpret_cast<const uint4*>(
                    g_Wfcb + (size_t)row * HID + k0) + c8);
            *(reinterpret_cast<uint4*>(Bs + row * FC_ASTR) + c8) = v;
        }
        __syncthreads();
#pragma unroll
        for (int ks = 0; ks < 4; ++ks) {
            int kk = ks * 16;
            unsigned a0, a1, a2, a3;
            unsigned addr = as_u +
                (unsigned)(((wid * 16 + (lane & 15)) * FC_ASTR + kk + ((lane >> 4) << 3)) * 2);
            LDMATRIX_X4(a0, a1, a2, a3, addr);
#pragma unroll
            for (int nf = 0; nf < 11; ++nf) {
                int n = nf * 8 + (lane >> 2);
                unsigned baddr = bs_u +
                    (unsigned)((n * FC_ASTR + kk + ((lane & 3) << 1)) * 2);
                unsigned b0r, b1r;
                asm volatile("ld.shared.b32 %0, [%1];" : "=r"(b0r) : "r"(baddr));
                asm volatile("ld.shared.b32 %0, [%1];" : "=r"(b1r) : "r"(baddr + 16));
                MMA_BF16(acc[nf], a0, a1, a2, a3, b0r, b1r);
            }
        }
    }

#pragma unroll
    for (int half = 0; half < 2; ++half) {
        int r  = wid * 16 + (lane >> 2) + half * 8;
        int tb = r0 + r;
        int t  = tb >> 7;
        int b  = tb & 127;
        bool m = t < __ldg(lens + b);
        size_t obase = ((size_t)b * T_STEPS + t) * CLS * 2;
#pragma unroll
        for (int nf = 0; nf < 11; ++nf) {
            int c = nf * 8 + ((lane & 3) << 1);
            float l0 = acc[nf][half * 2 + 0] + __ldg(bfc + c);
            float l1 = acc[nf][half * 2 + 1] + __ldg(bfc + c + 1);
            if (!m) { l0 = 0.f; l1 = 0.f; }
            float4 v = make_float4(l0, 1.f - l0, l1, 1.f - l1);
            *reinterpret_cast<float4*>(out + obase + (size_t)c * 2) = v;
        }
    }
}

// ---------------- launch ----------------
extern "C" void kernel_launch(void* const* d_in, const int* in_sizes, int n_in,
                              void* d_out, int out_size) {
    const float* x    = (const float*)d_in[0];
    const int*   lens = (const int*)d_in[1];    // int32 (JAX x64 disabled)
    const float* Wih  = (const float*)d_in[2];
    const float* Whh  = (const float*)d_in[3];
    const float* bih  = (const float*)d_in[4];
    const float* bhh  = (const float*)d_in[5];
    const float* Wfc  = (const float*)d_in[6];
    const float* bfc  = (const float*)d_in[7];
    float*       out  = (float*)d_out;
    (void)in_sizes; (void)n_in; (void)out_size;

    // lstm_kernel is the 4th launch (ncu capture slot)
    init_kernel<<<64, 256>>>();
    {
        size_t tot = (size_t)4096 * KP;
        prep_all_kernel<<<(unsigned)((tot + 255) / 256), 256>>>(Wih, Whh, bih, bhh, Wfc);
    }
    {
        size_t tot = (size_t)T_STEPS * BATCH * FEAT;
        prep_x_kernel<<<(unsigned)((tot + 255) / 256), 256>>>(x);
    }

    int smem = 64 * WS_STRIDE * 2          // resident W slice   (149504)
             + 4 * 64 * ASTR * 2           // A-stage ring B0-B3 (69632; B3 doubles as gsm)
             + 64 * 4 + 64 * 4;            // bias + lengths
    cudaFuncSetAttribute(lstm_kernel, cudaFuncAttributeMaxDynamicSharedMemorySize, smem);
    lstm_kernel<<<NCTA, NTHR, smem>>>(lens);

    fc_kernel<<<(T_STEPS * BATCH) / 64, 128>>>(lens, bfc, out);
}